// round 3
// baseline (speedup 1.0000x reference)
#include <cuda_runtime.h>
#include <math.h>

// ROI max pooling (Fast R-CNN convention), bit-exact vs the JAX/XLA reference.
//   x:    (B=4, C=256, H=50, W=50) float32
//   rois: (M, 5) float32  [batch_idx, x1, y1, x2, y2] in image coords
//   out:  (M, C, 7, 7) float32
//
// Numeric contract (established R2, bit-exact): coords * 0.0625f then
// __float2int_rn (round-half-even); bin size via multiply by RN(1/7)
// (XLA turns /7 into *recip); floor/ceil bin edges; clip to [0,50];
// empty bin -> 0.
//
// R3 structure: grid = (49, M). blockIdx.y = ROI. 14 threads decode the ROI
// bounds into shared memory once per block; all 256 threads then do pure
// max-gather work. Output mapping unchanged (coalesced).

#define POOL 7

static constexpr int   kC = 256;
static constexpr int   kH = 50;
static constexpr int   kW = 50;
static constexpr float kScale = 0.0625f;

__global__ void __launch_bounds__(256, 8)
roi_pool_kernel(const float* __restrict__ x,
                const float* __restrict__ rois,
                float* __restrict__ out)
{
    __shared__ int2 hb[POOL];   // (hs, he) per ph
    __shared__ int2 wb[POOL];   // (ws, we) per pw
    __shared__ int  sb;         // batch index

    const int m = blockIdx.y;
    const int t = threadIdx.x;

    if (t < 14) {
        const float* r = rois + (size_t)m * 5;
        int x1 = __float2int_rn(r[1] * kScale);
        int y1 = __float2int_rn(r[2] * kScale);
        int x2 = __float2int_rn(r[3] * kScale);
        int y2 = __float2int_rn(r[4] * kScale);

        float roi_h = (float)max(y2 - y1 + 1, 1);
        float roi_w = (float)max(x2 - x1 + 1, 1);
        const float kInv7 = 1.0f / 7.0f;           // RN(1/7), matches XLA
        float bh = roi_h * kInv7;
        float bw = roi_w * kInv7;

        if (t < POOL) {
            int i  = t;
            int hs = min(max((int)floorf((float)i * bh)       + y1, 0), kH);
            int he = min(max((int)ceilf((float)(i + 1) * bh)  + y1, 0), kH);
            hb[i] = make_int2(hs, he);
            if (t == 0) sb = (int)r[0];
        } else {
            int j  = t - POOL;
            int ws = min(max((int)floorf((float)j * bw)       + x1, 0), kW);
            int we = min(max((int)ceilf((float)(j + 1) * bw)  + x1, 0), kW);
            wb[j] = make_int2(ws, we);
        }
    }
    __syncthreads();

    // idx in [0, C*49): c = idx/49, bin = idx%49, ph = bin/7, pw = bin%7
    const int idx = blockIdx.x * 256 + t;          // gridDim.x = 49 exactly
    const int c   = idx / 49;
    const int bin = idx - c * 49;
    const int ph  = bin / POOL;
    const int pw  = bin - ph * POOL;

    const int2 hh = hb[ph];
    const int2 ww = wb[pw];

    const float* __restrict__ feat =
        x + ((size_t)sb * kC + c) * (kH * kW);

    float v = -INFINITY;
    for (int h = hh.x; h < hh.y; ++h) {
        const float* __restrict__ row = feat + h * kW + ww.x;
        for (int w = ww.x; w < ww.y; ++w) {
            v = fmaxf(v, __ldg(row));
            ++row;
        }
    }

    bool valid = (hh.y > hh.x) && (ww.y > ww.x);
    out[(size_t)m * (kC * 49) + idx] = valid ? v : 0.0f;
}

extern "C" void kernel_launch(void* const* d_in, const int* in_sizes, int n_in,
                              void* d_out, int out_size)
{
    const float* x    = (const float*)d_in[0];
    const float* rois = (const float*)d_in[1];
    float*       out  = (float*)d_out;

    int M = in_sizes[1] / 5;
    dim3 grid(49, M);            // 49*256 = C*7*7 outputs per ROI
    roi_pool_kernel<<<grid, 256>>>(x, rois, out);
}